// round 3
// baseline (speedup 1.0000x reference)
#include <cuda_runtime.h>
#include <math.h>

#define Tt   512
#define Bb   64
#define INN  128
#define Hh   512
#define Ll   3
#define OUTN 128

// ---------------- scratch (device globals: no runtime allocation) ----------
__device__ float g_bufA[Tt * Bb * Hh];   // 64 MB activation ping
__device__ float g_bufB[Tt * Bb * Hh];   // 64 MB activation pong
__device__ float g_hbuf[2][Bb * Hh];     // double-buffered hidden state
__device__ unsigned g_bar_count;         // grid barrier arrival count (self-resets)
__device__ unsigned g_bar_gen;           // grid barrier generation (monotonic)

// ---------------- software grid barrier (all CTAs co-resident) -------------
__device__ __forceinline__ void grid_barrier(unsigned* gen)
{
    __syncthreads();
    if (threadIdx.x == 0) {
        __threadfence();                       // publish this CTA's global writes
        unsigned target = *gen + 1;
        if (atomicAdd(&g_bar_count, 1) == gridDim.x - 1) {
            g_bar_count = 0;                   // reset for next phase
            __threadfence();
            atomicExch(&g_bar_gen, target);    // release
        } else {
            volatile unsigned* vp = &g_bar_gen;
            while (*vp != target) { }
            __threadfence();                   // acquire
        }
        *gen = target;
    }
    __syncthreads();
}

// ---------------- SGEMM: Y[M,N] = X[M,K] @ W[N,K]^T + b1(+b2) --------------
// BM=128, BN=64, BK=32, 256 threads, 8x4 microtile. M%128==0, N%64==0, K%32==0.
template <int K>
__global__ __launch_bounds__(256) void sgemm_bias(
    const float* __restrict__ X, const float* __restrict__ W,
    const float* __restrict__ b1, const float* __restrict__ b2,
    float* __restrict__ Y, int N)
{
    constexpr int BM = 128, BN = 64, BK = 32;
    __shared__ float Asm[BM * (BK + 1)];   // padded stride 33: conflict-free
    __shared__ float Wsm[BN * (BK + 1)];

    const int tid = threadIdx.x;
    const int r = tid >> 4;      // 0..15 -> 8 rows each
    const int c = tid & 15;      // 0..15 -> 4 cols each (strided by 16)
    const int m0 = blockIdx.y * BM;
    const int n0 = blockIdx.x * BN;

    float acc[8][4];
#pragma unroll
    for (int i = 0; i < 8; i++)
#pragma unroll
        for (int j = 0; j < 4; j++) acc[i][j] = 0.f;

    for (int k0 = 0; k0 < K; k0 += BK) {
        // A tile: 128x32 floats, coalesced float4 loads, scalar padded stores
#pragma unroll
        for (int i = 0; i < 4; i++) {
            int f = tid + i * 256;            // 0..1023 float4 slots
            int m = f >> 3, kq = f & 7;
            float4 v = *(const float4*)&X[(size_t)(m0 + m) * K + k0 + kq * 4];
            float* d = &Asm[m * (BK + 1) + kq * 4];
            d[0] = v.x; d[1] = v.y; d[2] = v.z; d[3] = v.w;
        }
        // W tile: 64x32 floats
#pragma unroll
        for (int i = 0; i < 2; i++) {
            int f = tid + i * 256;            // 0..511 float4 slots
            int n = f >> 3, kq = f & 7;
            float4 v = *(const float4*)&W[(size_t)(n0 + n) * K + k0 + kq * 4];
            float* d = &Wsm[n * (BK + 1) + kq * 4];
            d[0] = v.x; d[1] = v.y; d[2] = v.z; d[3] = v.w;
        }
        __syncthreads();

#pragma unroll
        for (int kk = 0; kk < BK; kk++) {
            float a[8], b[4];
#pragma unroll
            for (int i = 0; i < 8; i++) a[i] = Asm[(r * 8 + i) * (BK + 1) + kk];
#pragma unroll
            for (int j = 0; j < 4; j++) b[j] = Wsm[(j * 16 + c) * (BK + 1) + kk];
#pragma unroll
            for (int i = 0; i < 8; i++)
#pragma unroll
                for (int j = 0; j < 4; j++) acc[i][j] += a[i] * b[j];
        }
        __syncthreads();
    }

#pragma unroll
    for (int i = 0; i < 8; i++) {
        int m = m0 + r * 8 + i;
#pragma unroll
        for (int j = 0; j < 4; j++) {
            int n = n0 + j * 16 + c;
            float bias = b1[n];
            if (b2) bias += b2[n];
            Y[(size_t)m * N + n] = acc[i][j] + bias;
        }
    }
}

// ---------------- recurrent scan ------------------------------------------
// act: [T,B,H] holds pre (with biases folded); overwritten in place with ys.
// 128 CTAs = 16 b-groups x 8 j-groups. CTA tile: 4 batches x 64 columns.
// W_hh slice (64 cols x 512 k) resident in shared memory for the whole kernel.
// 256 threads = 16 jq (4 j each) x 16 ks (32 k each), smem k-split reduction.
#define SCAN_SMEM ((64 * Hh + 4 * Hh + 16 * 256) * 4)

__global__ __launch_bounds__(256) void rnn_scan(
    float* __restrict__ act,
    const float* __restrict__ Whh,   // [H,H] row-major (j,k)
    const float* __restrict__ h0l,   // [B,H]
    float* __restrict__ hout)        // [B,H] final hidden
{
    extern __shared__ float sm[];
    float* Wsm = sm;                 // [512 k][64 j], j fastest
    float* hsm = sm + 64 * Hh;       // [4 b][512 k]
    float* red = hsm + 4 * Hh;       // [16 ks][4 b * 64 j]

    const int tid = threadIdx.x;
    const int jq  = tid & 15;        // 0..15
    const int ks  = tid >> 4;        // 0..15
    const int jg  = blockIdx.x & 7;
    const int bg  = blockIdx.x >> 3;
    const int j0  = jg * 64;
    const int b0  = bg * 4;

    // load W slice once: Wsm[k*64 + j] = Whh[(j0+j)*H + k]
    for (int idx = tid; idx < 64 * Hh; idx += 256) {
        int j = idx >> 9, k = idx & 511;
        Wsm[k * 64 + j] = Whh[(size_t)(j0 + j) * Hh + k];
    }
    // copy this CTA's h0 tile into hidden buffer 0
    {
        int b = tid >> 6, j = tid & 63;    // 256 threads = 4x64 tile exactly
        g_hbuf[0][(b0 + b) * Hh + j0 + j] = h0l[(b0 + b) * Hh + j0 + j];
    }

    unsigned gen = 0;
    if (tid == 0) gen = *(volatile unsigned*)&g_bar_gen;   // replay-safe base
    grid_barrier(&gen);

    const int ob = tid >> 6;     // reduce-phase output mapping
    const int oj = tid & 63;

    const float4* wp = (const float4*)&Wsm[(ks * 32) * 64 + jq * 4];
    const float*  hp = &hsm[ks * 32];

    for (int t = 0; t < Tt; t++) {
        const float* hsrc = g_hbuf[t & 1];
        // load hsm[b][k] tile (4 x 512 floats) coalesced
#pragma unroll
        for (int i = 0; i < 2; i++) {
            int f = tid + i * 256;                 // 0..511 float4 slots
            int b = f >> 7, k4 = f & 127;
            *(float4*)&hsm[b * Hh + k4 * 4] =
                *(const float4*)&hsrc[(b0 + b) * Hh + k4 * 4];
        }
        __syncthreads();

        float acc[4][4];
#pragma unroll
        for (int b = 0; b < 4; b++)
#pragma unroll
            for (int jj = 0; jj < 4; jj++) acc[b][jj] = 0.f;

#pragma unroll
        for (int kk = 0; kk < 32; kk++) {
            float4 w = wp[kk * 16];                // Wsm[(ks*32+kk)*64 + jq*4]
            float ha = hp[kk];
            float hb = hp[512 + kk];
            float hc = hp[1024 + kk];
            float hd = hp[1536 + kk];
            acc[0][0] += ha * w.x; acc[0][1] += ha * w.y; acc[0][2] += ha * w.z; acc[0][3] += ha * w.w;
            acc[1][0] += hb * w.x; acc[1][1] += hb * w.y; acc[1][2] += hb * w.z; acc[1][3] += hb * w.w;
            acc[2][0] += hc * w.x; acc[2][1] += hc * w.y; acc[2][2] += hc * w.z; acc[2][3] += hc * w.w;
            acc[3][0] += hd * w.x; acc[3][1] += hd * w.y; acc[3][2] += hd * w.z; acc[3][3] += hd * w.w;
        }

        // k-split partials -> smem
#pragma unroll
        for (int b = 0; b < 4; b++)
            *(float4*)&red[ks * 256 + b * 64 + jq * 4] =
                make_float4(acc[b][0], acc[b][1], acc[b][2], acc[b][3]);
        __syncthreads();

        // reduce 16 partials, add pre, tanh, publish
        float s = 0.f;
#pragma unroll
        for (int q = 0; q < 16; q++) s += red[q * 256 + tid];

        int gb = b0 + ob, gj = j0 + oj;
        size_t gidx = (size_t)t * Bb * Hh + (size_t)gb * Hh + gj;
        float v = tanhf(s + act[gidx]);
        act[gidx] = v;                                    // ys in place
        g_hbuf[(t + 1) & 1][(size_t)gb * Hh + gj] = v;    // next-step h
        if (t == Tt - 1) hout[(size_t)gb * Hh + gj] = v;  // final hidden

        if (t < Tt - 1) grid_barrier(&gen);
    }
}

// ---------------- launch ----------------------------------------------------
extern "C" void kernel_launch(void* const* d_in, const int* in_sizes, int n_in,
                              void* d_out, int out_size)
{
    (void)in_sizes; (void)n_in; (void)out_size;
    const float* x     = (const float*)d_in[0];   // [T,B,IN]
    const float* h0    = (const float*)d_in[1];   // [L,B,H]
    const float* W_ih0 = (const float*)d_in[2];   // [H,IN]
    const float* W_ihr = (const float*)d_in[3];   // [L-1,H,H]
    const float* W_hh  = (const float*)d_in[4];   // [L,H,H]
    const float* b_ih  = (const float*)d_in[5];   // [L,H]
    const float* b_hh  = (const float*)d_in[6];   // [L,H]
    const float* lin_W = (const float*)d_in[7];   // [OUT,H]
    const float* lin_b = (const float*)d_in[8];   // [OUT]

    float* out   = (float*)d_out;                       // [T,B,OUT]
    float* h_out = out + (size_t)Tt * Bb * OUTN;        // [L,B,H]

    float *bufA, *bufB;
    cudaGetSymbolAddress((void**)&bufA, g_bufA);
    cudaGetSymbolAddress((void**)&bufB, g_bufB);

    cudaFuncSetAttribute(rnn_scan, cudaFuncAttributeMaxDynamicSharedMemorySize,
                         SCAN_SMEM);

    dim3 blk(256);
    const int MB = (Tt * Bb) / 128;     // 256 M-blocks

    // layer 0
    sgemm_bias<INN><<<dim3(Hh / 64, MB), blk>>>(x, W_ih0, b_ih, b_hh, bufA, Hh);
    rnn_scan<<<128, blk, SCAN_SMEM>>>(bufA, W_hh, h0, h_out);

    // layer 1
    sgemm_bias<Hh><<<dim3(Hh / 64, MB), blk>>>(bufA, W_ihr, b_ih + Hh, b_hh + Hh,
                                               bufB, Hh);
    rnn_scan<<<128, blk, SCAN_SMEM>>>(bufB, W_hh + Hh * Hh, h0 + Bb * Hh,
                                      h_out + Bb * Hh);

    // layer 2
    sgemm_bias<Hh><<<dim3(Hh / 64, MB), blk>>>(bufB, W_ihr + Hh * Hh,
                                               b_ih + 2 * Hh, b_hh + 2 * Hh,
                                               bufA, Hh);
    rnn_scan<<<128, blk, SCAN_SMEM>>>(bufA, W_hh + 2 * Hh * Hh, h0 + 2 * Bb * Hh,
                                      h_out + 2 * Bb * Hh);

    // final linear: [32768,512] @ [128,512]^T + lin_b -> d_out
    sgemm_bias<Hh><<<dim3(OUTN / 64, MB), blk>>>(bufA, lin_W, lin_b, nullptr,
                                                 out, OUTN);
}

// round 4
// speedup vs baseline: 1.4421x; 1.4421x over previous
#include <cuda_runtime.h>
#include <math.h>

#define Tt   512
#define Bb   64
#define INN  128
#define Hh   512
#define Ll   3
#define OUTN 128

// ---------------- scratch (device globals: no runtime allocation) ----------
__device__ float g_bufA[Tt * Bb * Hh];   // 64 MB activation ping
__device__ float g_bufB[Tt * Bb * Hh];   // 64 MB activation pong
__device__ float g_hbuf[2][Bb * Hh];     // double-buffered hidden state
__device__ unsigned g_flag[16][32];      // per-group producer flags (padded rows)

// ---------------- packed fp32x2 helpers (B300 FFMA2 path) ------------------
typedef unsigned long long ull;
#define FMA2(d, a, b) asm("fma.rn.f32x2 %0, %1, %2, %0;" : "+l"(d) : "l"(a), "l"(b))
#define UNPK(lo, hi, p) asm("mov.b64 {%0, %1}, %2;" : "=f"(lo), "=f"(hi) : "l"(p))

// ---------------- SGEMM: Y[M,N] = X[M,K] @ W[N,K]^T + b1(+b2) --------------
// BM=128, BN=64, BK=32, 256 threads, 8x4 microtile, packed f32x2 along k.
template <int K>
__global__ __launch_bounds__(256) void sgemm_bias(
    const float* __restrict__ X, const float* __restrict__ W,
    const float* __restrict__ b1, const float* __restrict__ b2,
    float* __restrict__ Y, int N)
{
    constexpr int BM = 128, BN = 64, BK = 32, SA = BK + 2;   // stride 34
    __shared__ float Asm[BM * SA];
    __shared__ float Wsm[BN * SA];

    const int tid = threadIdx.x;
    const int r = tid >> 4;      // 0..15 -> 8 rows each
    const int c = tid & 15;      // 0..15 -> 4 cols each (strided by 16)
    const int m0 = blockIdx.y * BM;
    const int n0 = blockIdx.x * BN;

    ull acc[8][4];
#pragma unroll
    for (int i = 0; i < 8; i++)
#pragma unroll
        for (int j = 0; j < 4; j++) acc[i][j] = 0ull;

    for (int k0 = 0; k0 < K; k0 += BK) {
        // A tile: 128x32 floats, coalesced float4 loads, float2 padded stores
#pragma unroll
        for (int i = 0; i < 4; i++) {
            int f = tid + i * 256;            // 0..1023 float4 slots
            int m = f >> 3, kq = f & 7;
            float4 v = *(const float4*)&X[(size_t)(m0 + m) * K + k0 + kq * 4];
            float* d = &Asm[m * SA + kq * 4];
            *(float2*)&d[0] = make_float2(v.x, v.y);
            *(float2*)&d[2] = make_float2(v.z, v.w);
        }
        // W tile: 64x32 floats
#pragma unroll
        for (int i = 0; i < 2; i++) {
            int f = tid + i * 256;            // 0..511 float4 slots
            int n = f >> 3, kq = f & 7;
            float4 v = *(const float4*)&W[(size_t)(n0 + n) * K + k0 + kq * 4];
            float* d = &Wsm[n * SA + kq * 4];
            *(float2*)&d[0] = make_float2(v.x, v.y);
            *(float2*)&d[2] = make_float2(v.z, v.w);
        }
        __syncthreads();

#pragma unroll
        for (int kp = 0; kp < BK / 2; kp++) {
            ull a[8], b[4];
#pragma unroll
            for (int i = 0; i < 8; i++)
                a[i] = *(const ull*)&Asm[(r * 8 + i) * SA + 2 * kp];
#pragma unroll
            for (int j = 0; j < 4; j++)
                b[j] = *(const ull*)&Wsm[(j * 16 + c) * SA + 2 * kp];
#pragma unroll
            for (int i = 0; i < 8; i++)
#pragma unroll
                for (int j = 0; j < 4; j++) FMA2(acc[i][j], a[i], b[j]);
        }
        __syncthreads();
    }

#pragma unroll
    for (int i = 0; i < 8; i++) {
        int m = m0 + r * 8 + i;
#pragma unroll
        for (int j = 0; j < 4; j++) {
            int n = n0 + j * 16 + c;
            float lo, hi;
            UNPK(lo, hi, acc[i][j]);
            float bias = b1[n];
            if (b2) bias += b2[n];
            Y[(size_t)m * N + n] = lo + hi + bias;
        }
    }
}

// ---------------- recurrent scan ------------------------------------------
// 128 CTAs = 16 batch-groups (bg) x 8 j-groups (jg). CTA tile: 4 b x 64 j.
// Cross-CTA dependency is batch-group-local: only 8-CTA flag barriers.
// W_hh slice held in REGISTERS (2 j rows x 64 k per thread, packed f32x2).
// 256 threads = 32 jq (2 j each) x 8 ks (64 k each); 8-way smem k-reduction.
__global__ __launch_bounds__(256) void rnn_scan(
    float* __restrict__ act,         // [T,B,H] pre -> overwritten with ys
    const float* __restrict__ Whh,   // [H,H] row-major (j,k)
    const float* __restrict__ h0l,   // [B,H]
    float* __restrict__ hout)        // [B,H] final hidden
{
    __shared__ float hsm[4 * Hh];    // [4 b][512 k]
    __shared__ float red[8 * 256];   // [8 ks][4 b * 64 j]
    __shared__ unsigned sbase;

    const int tid = threadIdx.x;
    const int jq  = tid & 31;        // 0..31 -> 2 j each
    const int ks  = tid >> 5;        // 0..7  -> 64 k each
    const int jg  = blockIdx.x & 7;
    const int bg  = blockIdx.x >> 3;
    const int j0  = jg * 64;
    const int b0  = bg * 4;
    const int kbase = ks * 64;

    // ---- load this thread's W slice into registers (persistent) ----
    ull w0[32], w1[32];
    {
        const float* r0 = &Whh[(size_t)(j0 + 2 * jq + 0) * Hh + kbase];
        const float* r1 = &Whh[(size_t)(j0 + 2 * jq + 1) * Hh + kbase];
#pragma unroll
        for (int kp = 0; kp < 32; kp++) {
            w0[kp] = *(const ull*)&r0[2 * kp];
            w1[kp] = *(const ull*)&r1[2 * kp];
        }
    }

    // ---- replay-safe flag base + h0 publish ----
    if (tid == 0) sbase = g_flag[bg][jg];       // all group flags equal at entry
    {
        int b = tid >> 6, j = tid & 63;          // 256 threads = 4x64 tile
        g_hbuf[0][(b0 + b) * Hh + j0 + j] = h0l[(b0 + b) * Hh + j0 + j];
    }
    __syncthreads();
    const unsigned base = sbase;
    if (tid == 0) {
        __threadfence();
        *(volatile unsigned*)&g_flag[bg][jg] = base + 1;   // h[0] written
    }

    const int ob = tid >> 6;     // reduce-phase output mapping
    const int oj = tid & 63;
    const int gb = b0 + ob, gj = j0 + oj;

    for (int t = 0; t < Tt; t++) {
        // prefetch this thread's pre value (independent of the barrier)
        size_t gidx = (size_t)t * Bb * Hh + (size_t)gb * Hh + gj;
        float pre = act[gidx];

        // ---- wait for the 8 producers of h[t] (group-local barrier) ----
        if (tid < 8) {
            volatile unsigned* f = &g_flag[bg][tid];
            unsigned target = base + (unsigned)t + 1;
            while ((int)(*f - target) < 0) { }
        }
        __syncthreads();

        // ---- stage h[t] tile (4 x 512) into smem, L2-coherent loads ----
        const float* hsrc = g_hbuf[t & 1];
#pragma unroll
        for (int i = 0; i < 2; i++) {
            int f = tid + i * 256;                 // 0..511 float4 slots
            int b = f >> 7, k4 = f & 127;
            float4 v = __ldcg((const float4*)&hsrc[(b0 + b) * Hh + k4 * 4]);
            *(float4*)&hsm[b * Hh + k4 * 4] = v;
        }
        __syncthreads();

        // ---- packed FFMA2 GEMM slice: 4b x 2j x 64k per thread ----
        ull a00 = 0, a01 = 0, a10 = 0, a11 = 0;
        ull a20 = 0, a21 = 0, a30 = 0, a31 = 0;
#pragma unroll
        for (int kp = 0; kp < 32; kp++) {
            ull wa = w0[kp], wb = w1[kp];
            ull hb0 = *(const ull*)&hsm[0 * Hh + kbase + 2 * kp];
            ull hb1 = *(const ull*)&hsm[1 * Hh + kbase + 2 * kp];
            ull hb2 = *(const ull*)&hsm[2 * Hh + kbase + 2 * kp];
            ull hb3 = *(const ull*)&hsm[3 * Hh + kbase + 2 * kp];
            FMA2(a00, wa, hb0); FMA2(a01, wb, hb0);
            FMA2(a10, wa, hb1); FMA2(a11, wb, hb1);
            FMA2(a20, wa, hb2); FMA2(a21, wb, hb2);
            FMA2(a30, wa, hb3); FMA2(a31, wb, hb3);
        }

        // ---- horizontal add, 8-way k-split partials to smem ----
        {
            float lo, hi, s0, s1;
            float* rp = &red[ks * 256 + 2 * jq];
            UNPK(lo, hi, a00); s0 = lo + hi; UNPK(lo, hi, a01); s1 = lo + hi;
            *(float2*)&rp[0 * 64] = make_float2(s0, s1);
            UNPK(lo, hi, a10); s0 = lo + hi; UNPK(lo, hi, a11); s1 = lo + hi;
            *(float2*)&rp[1 * 64] = make_float2(s0, s1);
            UNPK(lo, hi, a20); s0 = lo + hi; UNPK(lo, hi, a21); s1 = lo + hi;
            *(float2*)&rp[2 * 64] = make_float2(s0, s1);
            UNPK(lo, hi, a30); s0 = lo + hi; UNPK(lo, hi, a31); s1 = lo + hi;
            *(float2*)&rp[3 * 64] = make_float2(s0, s1);
        }
        __syncthreads();

        float s = 0.f;
#pragma unroll
        for (int q = 0; q < 8; q++) s += red[q * 256 + tid];

        float v = tanhf(s + pre);
        act[gidx] = v;                                      // ys in place
        g_hbuf[(t + 1) & 1][(size_t)gb * Hh + gj] = v;      // next-step h
        if (t == Tt - 1) hout[(size_t)gb * Hh + gj] = v;    // final hidden

        __syncthreads();                                     // red reuse + writes done
        if (tid == 0) {
            __threadfence();
            *(volatile unsigned*)&g_flag[bg][jg] = base + (unsigned)t + 2;
        }
    }
}

// ---------------- launch ----------------------------------------------------
extern "C" void kernel_launch(void* const* d_in, const int* in_sizes, int n_in,
                              void* d_out, int out_size)
{
    (void)in_sizes; (void)n_in; (void)out_size;
    const float* x     = (const float*)d_in[0];   // [T,B,IN]
    const float* h0    = (const float*)d_in[1];   // [L,B,H]
    const float* W_ih0 = (const float*)d_in[2];   // [H,IN]
    const float* W_ihr = (const float*)d_in[3];   // [L-1,H,H]
    const float* W_hh  = (const float*)d_in[4];   // [L,H,H]
    const float* b_ih  = (const float*)d_in[5];   // [L,H]
    const float* b_hh  = (const float*)d_in[6];   // [L,H]
    const float* lin_W = (const float*)d_in[7];   // [OUT,H]
    const float* lin_b = (const float*)d_in[8];   // [OUT]

    float* out   = (float*)d_out;                       // [T,B,OUT]
    float* h_out = out + (size_t)Tt * Bb * OUTN;        // [L,B,H]

    float *bufA, *bufB;
    cudaGetSymbolAddress((void**)&bufA, g_bufA);
    cudaGetSymbolAddress((void**)&bufB, g_bufB);

    dim3 blk(256);
    const int MB = (Tt * Bb) / 128;     // 256 M-blocks

    // layer 0
    sgemm_bias<INN><<<dim3(Hh / 64, MB), blk>>>(x, W_ih0, b_ih, b_hh, bufA, Hh);
    rnn_scan<<<128, blk>>>(bufA, W_hh, h0, h_out);

    // layer 1
    sgemm_bias<Hh><<<dim3(Hh / 64, MB), blk>>>(bufA, W_ihr, b_ih + Hh, b_hh + Hh,
                                               bufB, Hh);
    rnn_scan<<<128, blk>>>(bufB, W_hh + Hh * Hh, h0 + Bb * Hh, h_out + Bb * Hh);

    // layer 2
    sgemm_bias<Hh><<<dim3(Hh / 64, MB), blk>>>(bufB, W_ihr + Hh * Hh,
                                               b_ih + 2 * Hh, b_hh + 2 * Hh,
                                               bufA, Hh);
    rnn_scan<<<128, blk>>>(bufA, W_hh + 2 * Hh * Hh, h0 + 2 * Bb * Hh,
                           h_out + 2 * Bb * Hh);

    // final linear: [32768,512] @ [128,512]^T + lin_b -> d_out
    sgemm_bias<Hh><<<dim3(OUTN / 64, MB), blk>>>(bufA, lin_W, lin_b, nullptr,
                                                 out, OUTN);
}